// round 17
// baseline (speedup 1.0000x reference)
#include <cuda_runtime.h>
#include <cuda_bf16.h>
#include <cuda_fp16.h>
#include <cuda_fp8.h>
#include <cstdint>

// NT-Xent loss. loss_i = -2*p_i + log(S_i - exp(2*d_i) + exp(2*p_i)),
// S_i = sum_j exp(2*sim[i,j]), sim = R R^T (symmetric -> lower triangle only).
// Round 16: 2 tiles/CTA along a triangle row (A loaded once, B double-buffered,
// cross-tile rowsum accumulation). FP8 e4m3 MMA, f16 acc, ex2.f16x2 epilogue.

#define NROWS 8192
#define HALF_N 4096
#define DIM 128

__device__ __align__(16) uint8_t g_R8[NROWS * DIM];   // e4m3, rows scaled by 16
__device__ float g_S[NROWS];
__device__ float g_pos[NROWS];
__device__ float g_diag[NROWS];   // diag of fp8 sim: ||q||^2 / 256

// ---- kernel 1: fused L2-normalize (both views) + pos/diag + init --------
__global__ void __launch_bounds__(128) k_fused(const float* __restrict__ zi,
                                               const float* __restrict__ zj,
                                               float* __restrict__ out) {
    int warp = (blockIdx.x * blockDim.x + threadIdx.x) >> 5;
    int lane = threadIdx.x & 31;
    if (blockIdx.x == 0 && threadIdx.x == 0) out[0] = 0.0f;
    if (warp >= HALF_N) return;
    int i = warp, j = warp + HALF_N;

    float4 vi = reinterpret_cast<const float4*>(zi + (size_t)i * DIM)[lane];
    float4 vj = reinterpret_cast<const float4*>(zj + (size_t)i * DIM)[lane];
    float si = vi.x * vi.x + vi.y * vi.y + vi.z * vi.z + vi.w * vi.w;
    float sj = vj.x * vj.x + vj.y * vj.y + vj.z * vj.z + vj.w * vj.w;
    #pragma unroll
    for (int o = 16; o; o >>= 1) {
        si += __shfl_xor_sync(0xffffffffu, si, o);
        sj += __shfl_xor_sync(0xffffffffu, sj, o);
    }
    float inv_i = rsqrtf(fmaxf(si, 1e-24f));
    float inv_j = rsqrtf(fmaxf(sj, 1e-24f));
    float ax = vi.x * inv_i, ay = vi.y * inv_i, az = vi.z * inv_i, aw = vi.w * inv_i;
    float bx = vj.x * inv_j, by = vj.y * inv_j, bz = vj.z * inv_j, bw = vj.w * inv_j;

    float p = ax * bx + ay * by + az * bz + aw * bw;  // fp32 positive

    uint32_t qi = (uint32_t)__nv_cvt_float_to_fp8(ax * 16.0f, __NV_SATFINITE, __NV_E4M3)
                | ((uint32_t)__nv_cvt_float_to_fp8(ay * 16.0f, __NV_SATFINITE, __NV_E4M3) << 8)
                | ((uint32_t)__nv_cvt_float_to_fp8(az * 16.0f, __NV_SATFINITE, __NV_E4M3) << 16)
                | ((uint32_t)__nv_cvt_float_to_fp8(aw * 16.0f, __NV_SATFINITE, __NV_E4M3) << 24);
    uint32_t qj = (uint32_t)__nv_cvt_float_to_fp8(bx * 16.0f, __NV_SATFINITE, __NV_E4M3)
                | ((uint32_t)__nv_cvt_float_to_fp8(by * 16.0f, __NV_SATFINITE, __NV_E4M3) << 8)
                | ((uint32_t)__nv_cvt_float_to_fp8(bz * 16.0f, __NV_SATFINITE, __NV_E4M3) << 16)
                | ((uint32_t)__nv_cvt_float_to_fp8(bw * 16.0f, __NV_SATFINITE, __NV_E4M3) << 24);
    reinterpret_cast<uint32_t*>(g_R8 + (size_t)i * DIM)[lane] = qi;
    reinterpret_cast<uint32_t*>(g_R8 + (size_t)j * DIM)[lane] = qj;

    // diag of fp8 similarity (exact cancellation vs GEMM diagonal)
    __half2_raw hi0 = __nv_cvt_fp8x2_to_halfraw2((__nv_fp8x2_storage_t)(qi & 0xFFFF), __NV_E4M3);
    __half2_raw hi1 = __nv_cvt_fp8x2_to_halfraw2((__nv_fp8x2_storage_t)(qi >> 16), __NV_E4M3);
    __half2_raw hj0 = __nv_cvt_fp8x2_to_halfraw2((__nv_fp8x2_storage_t)(qj & 0xFFFF), __NV_E4M3);
    __half2_raw hj1 = __nv_cvt_fp8x2_to_halfraw2((__nv_fp8x2_storage_t)(qj >> 16), __NV_E4M3);
    float2 fi0 = __half22float2(*reinterpret_cast<__half2*>(&hi0));
    float2 fi1 = __half22float2(*reinterpret_cast<__half2*>(&hi1));
    float2 fj0 = __half22float2(*reinterpret_cast<__half2*>(&hj0));
    float2 fj1 = __half22float2(*reinterpret_cast<__half2*>(&hj1));
    float di = fi0.x * fi0.x + fi0.y * fi0.y + fi1.x * fi1.x + fi1.y * fi1.y;
    float dj = fj0.x * fj0.x + fj0.y * fj0.y + fj1.x * fj1.x + fj1.y * fj1.y;

    #pragma unroll
    for (int o = 16; o; o >>= 1) {
        p  += __shfl_xor_sync(0xffffffffu, p, o);
        di += __shfl_xor_sync(0xffffffffu, di, o);
        dj += __shfl_xor_sync(0xffffffffu, dj, o);
    }
    if (lane == 0) {
        g_pos[i] = p;  g_pos[j] = p;
        g_diag[i] = di * (1.0f / 256.0f);
        g_diag[j] = dj * (1.0f / 256.0f);
        g_S[i] = 0.0f; g_S[j] = 0.0f;
    }
}

// ------------- kernel 2: lower-triangle FP8 MMA, 2 tiles per CTA ---------
#define SROW 144

__device__ __forceinline__ void mma_e4m3_f16(uint32_t* c, const uint32_t* a, const uint32_t* b) {
    asm volatile(
        "mma.sync.aligned.m16n8k32.row.col.f16.e4m3.e4m3.f16 "
        "{%0,%1}, {%2,%3,%4,%5}, {%6,%7}, {%0,%1};"
        : "+r"(c[0]), "+r"(c[1])
        : "r"(a[0]), "r"(a[1]), "r"(a[2]), "r"(a[3]), "r"(b[0]), "r"(b[1]));
}
__device__ __forceinline__ void ldsm_x4(uint32_t* r, uint32_t addr) {
    asm volatile("ldmatrix.sync.aligned.m8n8.x4.shared.b16 {%0,%1,%2,%3}, [%4];"
                 : "=r"(r[0]), "=r"(r[1]), "=r"(r[2]), "=r"(r[3]) : "r"(addr));
}
__device__ __forceinline__ __half2 h2_ex2(__half2 x) {
    uint32_t r, xi = *reinterpret_cast<uint32_t*>(&x);
    asm("ex2.approx.f16x2 %0, %1;" : "=r"(r) : "r"(xi));
    return *reinterpret_cast<__half2*>(&r);
}
__device__ __forceinline__ void cp16(uint32_t dst, const void* src) {
    asm volatile("cp.async.cg.shared.global [%0], [%1], 16;" :: "r"(dst), "l"(src));
}

__global__ void __launch_bounds__(256, 2) k_simexp() {
    __shared__ uint8_t As[128 * SROW];
    __shared__ uint8_t B0s[128 * SROW];
    __shared__ uint8_t B1s[128 * SROW];
    __shared__ float rowsum[128];
    __shared__ float colsum[128];

    int tid = threadIdx.x;
    int wid = tid >> 5, lane = tid & 31;
    int wm = wid >> 2, wn = wid & 3;      // 2x4 warp grid; warp tile 64x32
    int g = lane >> 2, tq = lane & 3;

    // pair-index -> (bi, bj0): row bi has ceil((bi+1)/2) CTAs; prefix T(bi) = (bi+1)^2/4
    int p = blockIdx.x;
    int bi = (int)(2.0f * sqrtf((float)p + 1.0f));
    while ((((bi + 1) * (bi + 1)) >> 2) > p) bi--;
    while ((((bi + 2) * (bi + 2)) >> 2) <= p) bi++;
    int bj0 = 2 * (p - (((bi + 1) * (bi + 1)) >> 2));
    bool two = (bj0 + 1 <= bi);

    uint32_t sA = (uint32_t)__cvta_generic_to_shared(As);
    uint32_t sB0 = (uint32_t)__cvta_generic_to_shared(B0s);
    uint32_t sB1 = (uint32_t)__cvta_generic_to_shared(B1s);

    // ---- issue all loads up front: group0 = A + B0, group1 = B1 ----
    {
        const uint4* gA = reinterpret_cast<const uint4*>(g_R8 + (size_t)(bi * 128) * DIM);
        const uint4* gB0 = reinterpret_cast<const uint4*>(g_R8 + (size_t)(bj0 * 128) * DIM);
        #pragma unroll
        for (int it = 0; it < 4; it++) {
            int idx = tid + 256 * it;
            int r = idx >> 3, c8 = idx & 7;
            uint32_t so = (uint32_t)(r * SROW + c8 * 16);
            cp16(sA + so, gA + idx);
            cp16(sB0 + so, gB0 + idx);
        }
        asm volatile("cp.async.commit_group;" ::: "memory");
        if (two) {
            const uint4* gB1 = reinterpret_cast<const uint4*>(g_R8 + (size_t)((bj0 + 1) * 128) * DIM);
            #pragma unroll
            for (int it = 0; it < 4; it++) {
                int idx = tid + 256 * it;
                int r = idx >> 3, c8 = idx & 7;
                uint32_t so = (uint32_t)(r * SROW + c8 * 16);
                cp16(sB1 + so, gB1 + idx);
            }
        }
        asm volatile("cp.async.commit_group;" ::: "memory");
    }
    if (tid < 128) { rowsum[tid] = 0.0f; colsum[tid] = 0.0f; }

    // fragment base offsets (within a tile buffer)
    uint32_t aBase = sA + (uint32_t)((wm * 64 + ((lane >> 3) & 1) * 8 + (lane & 7)) * SROW +
                                     ((lane >> 4) & 1) * 16);
    uint32_t bOff = (uint32_t)((wn * 32 + ((lane >> 4) & 1) * 8 + (lane & 7)) * SROW +
                               ((lane >> 3) & 1) * 16);
    const __half2 SC2 = __float2half2_rn(0.01127197452f);  // log2(e)/128

    auto do_tile = [&](uint32_t bBuf, int bj) {
        bool offdiag = (bj != bi);
        uint32_t c[4][4][2];
        #pragma unroll
        for (int mf = 0; mf < 4; mf++)
            #pragma unroll
            for (int nf = 0; nf < 4; nf++) { c[mf][nf][0] = 0u; c[mf][nf][1] = 0u; }

        uint32_t bBase = bBuf + bOff;
        #pragma unroll
        for (int kk = 0; kk < 128; kk += 32) {
            uint32_t a[4][4];
            #pragma unroll
            for (int mf = 0; mf < 4; mf++)
                ldsm_x4(a[mf], aBase + (uint32_t)(mf * 16 * SROW + kk));
            uint32_t b[4][2];
            #pragma unroll
            for (int nfp = 0; nfp < 2; nfp++) {
                uint32_t r[4];
                ldsm_x4(r, bBase + (uint32_t)(nfp * 16 * SROW + kk));
                b[2 * nfp][0] = r[0]; b[2 * nfp][1] = r[1];
                b[2 * nfp + 1][0] = r[2]; b[2 * nfp + 1][1] = r[3];
            }
            #pragma unroll
            for (int mf = 0; mf < 4; mf++)
                #pragma unroll
                for (int nf = 0; nf < 4; nf++)
                    mma_e4m3_f16(c[mf][nf], a[mf], b[nf]);
        }

        // epilogue: exp(2*sim) = 2^(c * log2e/128)
        __half2 cs2[4];
        #pragma unroll
        for (int nf = 0; nf < 4; nf++) cs2[nf] = __half2half2(__ushort_as_half(0));

        #pragma unroll
        for (int mf = 0; mf < 4; mf++) {
            __half2 r0h = __half2half2(__ushort_as_half(0));
            __half2 r1h = __half2half2(__ushort_as_half(0));
            #pragma unroll
            for (int nf = 0; nf < 4; nf++) {
                __half2 h0 = *reinterpret_cast<__half2*>(&c[mf][nf][0]);
                __half2 h1 = *reinterpret_cast<__half2*>(&c[mf][nf][1]);
                __half2 e0 = h2_ex2(__hmul2(h0, SC2));
                __half2 e1 = h2_ex2(__hmul2(h1, SC2));
                r0h = __hadd2(r0h, e0);
                r1h = __hadd2(r1h, e1);
                cs2[nf] = __hadd2(cs2[nf], __hadd2(e0, e1));
            }
            float2 f0 = __half22float2(r0h);
            float2 f1 = __half22float2(r1h);
            float rs0 = f0.x + f0.y;
            float rs1 = f1.x + f1.y;
            #pragma unroll
            for (int o = 1; o < 4; o <<= 1) {
                rs0 += __shfl_xor_sync(0xffffffffu, rs0, o);
                rs1 += __shfl_xor_sync(0xffffffffu, rs1, o);
            }
            if (tq == 0) {
                atomicAdd(&rowsum[wm * 64 + mf * 16 + g], rs0);
                atomicAdd(&rowsum[wm * 64 + mf * 16 + g + 8], rs1);
            }
        }
        if (offdiag) {
            #pragma unroll
            for (int nf = 0; nf < 4; nf++) {
                float2 f = __half22float2(cs2[nf]);
                float a = f.x, b = f.y;
                #pragma unroll
                for (int o = 4; o < 32; o <<= 1) {
                    a += __shfl_xor_sync(0xffffffffu, a, o);
                    b += __shfl_xor_sync(0xffffffffu, b, o);
                }
                if (lane < 4) {
                    atomicAdd(&colsum[wn * 32 + nf * 8 + lane * 2], a);
                    atomicAdd(&colsum[wn * 32 + nf * 8 + lane * 2 + 1], b);
                }
            }
        }
    };

    // ---- tile 0 ----
    asm volatile("cp.async.wait_group 1;" ::: "memory");
    __syncthreads();
    do_tile(sB0, bj0);
    __syncthreads();

    if (!two) {
        if (tid < 128) {
            if (bj0 != bi) atomicAdd(&g_S[bj0 * 128 + tid], colsum[tid]);
            atomicAdd(&g_S[bi * 128 + tid], rowsum[tid]);
        }
        return;
    }
    // flush tile-0 colsums, reset for tile 1
    if (tid < 128) {
        if (bj0 != bi) atomicAdd(&g_S[bj0 * 128 + tid], colsum[tid]);
        colsum[tid] = 0.0f;
    }

    // ---- tile 1 ----
    asm volatile("cp.async.wait_group 0;" ::: "memory");
    __syncthreads();
    do_tile(sB1, bj0 + 1);
    __syncthreads();

    if (tid < 128) {
        if (bj0 + 1 != bi) atomicAdd(&g_S[(bj0 + 1) * 128 + tid], colsum[tid]);
        atomicAdd(&g_S[bi * 128 + tid], rowsum[tid]);
    }
}

// ------------- kernel 3: finalize (parallel, warp-shuffle reduce) --------
__global__ void __launch_bounds__(128) k_final(float* __restrict__ out) {
    __shared__ float part[4];
    int tid = threadIdx.x;
    int i = blockIdx.x * 128 + tid;  // 64 blocks x 128 = 8192 rows
    float p = g_pos[i];
    float d = g_diag[i];
    float S = g_S[i];
    float denom = S - __expf(2.0f * d) + __expf(2.0f * p);
    float v = -2.0f * p + __logf(denom);
    #pragma unroll
    for (int o = 16; o; o >>= 1) v += __shfl_xor_sync(0xffffffffu, v, o);
    if ((tid & 31) == 0) part[tid >> 5] = v;
    __syncthreads();
    if (tid == 0) {
        float s = part[0] + part[1] + part[2] + part[3];
        atomicAdd(out, s * (1.0f / (float)NROWS));
    }
}

extern "C" void kernel_launch(void* const* d_in, const int* in_sizes, int n_in,
                              void* d_out, int out_size) {
    const float* zi = (const float*)d_in[0];
    const float* zj = (const float*)d_in[1];
    float* out = (float*)d_out;
    (void)in_sizes; (void)n_in; (void)out_size;

    k_fused<<<HALF_N / 4, 128>>>(zi, zj, out);  // normalize+quantize+pos/diag, init
    k_simexp<<<1056, 256>>>();                  // 2 lower-tri tiles per CTA
    k_final<<<64, 128>>>(out);
}